// round 17
// baseline (speedup 1.0000x reference)
#include <cuda_runtime.h>
#include <cuda_fp16.h>
#include <cstdint>

// Problem constants (fixed by dataset):
// b=2, s=256, C=128, H=W=16, YH=XH=CH=2 -> nH=8 heads, c=64, h=w=8, D=4096
// mask: 16x16 token grid, radius-1 neighborhood (<=9 keys per query)

#define NTOK   512
#define FDIM   4096
#define SLICE  (256*4096)
#define PITCH  72            // W smem row pitch in halfs (64 data + 8 pad)
#define PITCHB 136           // X smem row pitch in halfs (128 data + 8 pad)

typedef unsigned long long u64;

// Scratch (device globals -- allocation-free per harness rules)
__device__ __align__(16) __half g_qh[2*8*256*4096];
__device__ __align__(16) __half g_kh[2*8*256*4096];
__device__ __align__(16) __half g_vh[2*8*256*4096];
__device__ __align__(16) __half g_sah[512*256*128];   // fp16 sa, [t][p][C]
__device__ __align__(16) __half g_wth[3*128*128];     // fp16 w_qkv [d][k]
__device__ __align__(16) __half g_wtoh[128*128];      // fp16 w_out [d][k]

// ---------------------------------------------------------------------------
// helpers
// ---------------------------------------------------------------------------
__device__ __forceinline__ void cp16h(__half* smem_dst, const __half* gsrc) {
    uint32_t s = (uint32_t)__cvta_generic_to_shared(smem_dst);
    asm volatile("cp.async.ca.shared.global [%0], [%1], 16;" :: "r"(s), "l"(gsrc));
}

__device__ __forceinline__ void ldsm4(uint32_t* r, const __half* p) {
    uint32_t a = (uint32_t)__cvta_generic_to_shared(p);
    asm volatile("ldmatrix.sync.aligned.m8n8.x4.shared.b16 {%0,%1,%2,%3}, [%4];"
                 : "=r"(r[0]), "=r"(r[1]), "=r"(r[2]), "=r"(r[3]) : "r"(a));
}

__device__ __forceinline__ void ldsm4t(uint32_t* r, const __half* p) {
    uint32_t a = (uint32_t)__cvta_generic_to_shared(p);
    asm volatile("ldmatrix.sync.aligned.m8n8.x4.trans.shared.b16 {%0,%1,%2,%3}, [%4];"
                 : "=r"(r[0]), "=r"(r[1]), "=r"(r[2]), "=r"(r[3]) : "r"(a));
}

__device__ __forceinline__ void mma_f16(float* c, const uint32_t* a,
                                        uint32_t b0, uint32_t b1) {
    asm volatile(
        "mma.sync.aligned.m16n8k16.row.col.f32.f16.f16.f32 "
        "{%0,%1,%2,%3}, {%4,%5,%6,%7}, {%8,%9}, {%0,%1,%2,%3};"
        : "+f"(c[0]), "+f"(c[1]), "+f"(c[2]), "+f"(c[3])
        : "r"(a[0]), "r"(a[1]), "r"(a[2]), "r"(a[3]), "r"(b0), "r"(b1));
}

// ---- packed fp32 (B300 FFMA2 path) ----
__device__ __forceinline__ u64 pack2(float x, float y) {
    u64 r;
    asm("mov.b64 %0, {%1, %2};" : "=l"(r) : "f"(x), "f"(y));
    return r;
}
__device__ __forceinline__ void unpack2(u64 v, float& x, float& y) {
    asm("mov.b64 {%0, %1}, %2;" : "=f"(x), "=f"(y) : "l"(v));
}
__device__ __forceinline__ u64 ffma2(u64 a, u64 b, u64 c) {
    u64 d;
    asm("fma.rn.f32x2 %0, %1, %2, %3;" : "=l"(d) : "l"(a), "l"(b), "l"(c));
    return d;
}
__device__ __forceinline__ u64 h2tofx2(uint32_t h2bits) {
    float2 f = __half22float2(*reinterpret_cast<__half2*>(&h2bits));
    return pack2(f.x, f.y);
}

// ---------------------------------------------------------------------------
// prep_w: weight fp32 -> fp16
// ---------------------------------------------------------------------------
__global__ __launch_bounds__(256) void prep_w(const float* __restrict__ wq,
                                              const float* __restrict__ wo) {
    int i = blockIdx.x * 256 + threadIdx.x;   // grid 192 -> 49152
    g_wth[i] = __float2half_rn(wq[i]);
    if (i < 16384) g_wtoh[i] = __float2half_rn(wo[i]);
}

// ---------------------------------------------------------------------------
// Kernel A: QKV projection, dt-merged, X direct from seq via trans-ldmatrix
// (unchanged from R15/R16 pass). smem 104448 B.
// ---------------------------------------------------------------------------
__global__ __launch_bounds__(256, 2) void qkv_gemm(const float* __restrict__ seq) {
    const int t  = blockIdx.x;
    const int pt = blockIdx.y;
    const int tid = threadIdx.x;
    const int lane = tid & 31, wid = tid >> 5;
    const int wm = wid >> 1, wn = wid & 1;

    extern __shared__ __align__(16) __half smem[];
    __half* Xb   = smem;                 // [128 c][PITCHB]
    __half* Wbuf = smem + 17408;         // [2][128][72]
    uint32_t* sst = reinterpret_cast<uint32_t*>(smem + 35840);   // 8192 words

    auto issueW = [&](int dt) {
        const __half* wsrc = g_wth + dt * 16384;
        #pragma unroll
        for (int kt = 0; kt < 2; kt++) {
            #pragma unroll
            for (int i = 0; i < 4; i++) {
                int id = tid + i * 256;
                int row = id >> 3, seg = (id & 7) * 8;
                cp16h(Wbuf + kt * 9216 + row * PITCH + seg, wsrc + row * 128 + kt * 64 + seg);
            }
            asm volatile("cp.async.commit_group;" ::: "memory");
        }
    };
    issueW(0);

    {
        const float* xsrc = seq + (size_t)t * 32768 + pt * 128;
        #pragma unroll
        for (int j = 0; j < 16; j++) {
            int idx = tid + j * 256;
            int c = idx >> 5, p4 = (idx & 31) * 4;
            float4 v = *reinterpret_cast<const float4*>(xsrc + c * 256 + p4);
            __half2 h0 = __floats2half2_rn(v.x, v.y);
            __half2 h1 = __floats2half2_rn(v.z, v.w);
            uint2 u;
            u.x = *reinterpret_cast<uint32_t*>(&h0);
            u.y = *reinterpret_cast<uint32_t*>(&h1);
            *reinterpret_cast<uint2*>(Xb + c * PITCHB + p4) = u;
        }
    }

    const int l7 = lane & 7;
    const int aoff  = (l7 + ((lane >> 3) & 1) * 8) * PITCH  + ((lane >> 4) & 1) * 8;
    const int boffT = (l7 + ((lane >> 3) & 1) * 8) * PITCHB + ((lane >> 4) & 1) * 8;

    const int b_ = t >> 8, s_ = t & 255;

    #pragma unroll 1
    for (int dt = 0; dt < 3; dt++) {
        float acc[2][8][4];
        #pragma unroll
        for (int mf = 0; mf < 2; mf++)
            #pragma unroll
            for (int nf = 0; nf < 8; nf++)
                #pragma unroll
                for (int r = 0; r < 4; r++) acc[mf][nf][r] = 0.f;

        #pragma unroll
        for (int kt = 0; kt < 2; kt++) {
            if (kt == 0) asm volatile("cp.async.wait_group 1;" ::: "memory");
            else         asm volatile("cp.async.wait_group 0;" ::: "memory");
            __syncthreads();

            const __half* A = Wbuf + kt * 9216;

            #pragma unroll
            for (int k0 = 0; k0 < 64; k0 += 16) {
                const int gk = kt * 64 + k0;
                uint32_t af[2][4], bf[4][4];
                #pragma unroll
                for (int mf = 0; mf < 2; mf++)
                    ldsm4(af[mf], A + (wm * 32 + mf * 16) * PITCH + k0 + aoff);
                #pragma unroll
                for (int np = 0; np < 4; np++)
                    ldsm4t(bf[np], Xb + gk * PITCHB + wn * 64 + np * 16 + boffT);
                #pragma unroll
                for (int mf = 0; mf < 2; mf++)
                    #pragma unroll
                    for (int nf = 0; nf < 8; nf++)
                        mma_f16(acc[mf][nf], af[mf],
                                bf[nf >> 1][(nf & 1) * 2], bf[nf >> 1][(nf & 1) * 2 + 1]);
            }
        }
        __syncthreads();

        if (dt < 2) issueW(dt + 1);

        #pragma unroll
        for (int mf = 0; mf < 2; mf++) {
            #pragma unroll
            for (int h8 = 0; h8 < 2; h8++) {
                const int dl = wm * 32 + mf * 16 + (lane >> 2) + h8 * 8;
                const int ch = dl >> 6, cidx = dl & 63;
                #pragma unroll
                for (int nf = 0; nf < 8; nf++) {
                    const int xs = nf & 1;
                    const int hy = wn * 4 + (nf >> 1);
                    const int hidx = xs * 2 + ch;
                    __half2 hv = __floats2half2_rn(acc[mf][nf][h8 * 2],
                                                   acc[mf][nf][h8 * 2 + 1]);
                    const int word = hidx * 2048 + cidx * 32
                                   + ((hy ^ (cidx & 7)) << 2) + (lane & 3);
                    sst[word] = *reinterpret_cast<uint32_t*>(&hv);
                }
            }
        }
        __syncthreads();

        __half* dst = (dt == 0) ? g_qh : (dt == 1) ? g_kh : g_vh;
        const uint4* sst4 = reinterpret_cast<const uint4*>(sst);
        #pragma unroll
        for (int i = 0; i < 8; i++) {
            const int idx = tid + i * 256;
            const int hidx = idx >> 9, g = idx & 511;
            const int cidx = g >> 3, hy = g & 7;
            const int src = hidx * 512 + cidx * 8 + (hy ^ (cidx & 7));
            const int xs = hidx >> 1, ch = hidx & 1;
            const int n = (pt * 2 + xs) * 2 + ch;
            const size_t base = ((size_t)((b_ * 8 + n) * 256 + s_)) * FDIM + g * 8;
            *reinterpret_cast<uint4*>(dst + base) = sst4[src];
        }
    }
}

// ---------------------------------------------------------------------------
// Kernel B: masked attention. Changes vs R16:
//  - BOTH k and v streamed through depth-4 cp.async rings (per-thread slices,
//    zero barriers in the streaming path) -> L2 latency hidden without regs
//  - score phase skips invalid tiles entirely (uniform predicate)
// Dynamic smem (83712 B), region layout (floats):
//   [0, 16640)    ssa[4][64][65] alias region; k-ring at bytes [0,32768),
//                 v-ring at bytes [32768,65536)
//   [16640,20800) red2[16][4][65]
//   [20800,20864) s_sc[16][4]
//   [20864,20928) s_w[4][16]
// ---------------------------------------------------------------------------
__global__ __launch_bounds__(512, 2) void attn_kernel() {
    const int blk = blockIdx.x;
    const int txq = blk & 7;
    const int tyq = (blk >> 3) & 7;
    const int n   = (blk >> 6) & 7;
    const int b_  = blk >> 9;
    const int tid = threadIdx.x;
    const int lane = tid & 31, wid = tid >> 5;

    extern __shared__ float smf[];
    __half* kring         = (__half*)smf;                     // 4 slots x 4096 halfs
    __half* vring         = (__half*)smf + 16384;             // 4 slots x 4096 halfs
    float (*red2)[4][65]  = (float (*)[4][65])(smf + 16640);
    float (*s_sc)[4]      = (float (*)[4])(smf + 20800);
    float (*s_w)[16]      = (float (*)[16])(smf + 20864);
    float (*ssa)[64][65]  = (float (*)[64][65])smf;           // aliases rings

    const int qy0 = tyq * 2, qx0 = txq * 2;
    const size_t slice = (size_t)(b_ * 8 + n) * SLICE;
    const int j_safe = qy0 * 16 + qx0;

    auto jof = [&](int e, bool& valid) {
        const int ky = qy0 - 1 + (e >> 2), kx = qx0 - 1 + (e & 3);
        valid = (ky >= 0) & (ky < 16) & (kx >= 0) & (kx < 16);
        return valid ? (ky * 16 + kx) : j_safe;
    };

    // issue k tiles 0..3 into the ring
    #pragma unroll
    for (int e = 0; e < 4; e++) {
        bool v_; const int j = jof(e, v_);
        cp16h(kring + (e & 3) * 4096 + tid * 8, g_kh + slice + (size_t)j * FDIM + tid * 8);
        asm volatile("cp.async.commit_group;" ::: "memory");
    }

    // q for 4 queries: native fp16 (4 x uint4)
    uint4 qv[4];
    #pragma unroll
    for (int qq = 0; qq < 4; qq++) {
        const int i = (qy0 + (qq >> 1)) * 16 + qx0 + (qq & 1);
        qv[qq] = *((const uint4*)(g_qh + slice + (size_t)i * FDIM) + tid);
    }

    // ---- scores: 16 k tiles through the ring ----
    #pragma unroll
    for (int e = 0; e < 16; e++) {
        if (e < 13)      asm volatile("cp.async.wait_group 3;" ::: "memory");
        else if (e == 13) asm volatile("cp.async.wait_group 2;" ::: "memory");
        else if (e == 14) asm volatile("cp.async.wait_group 1;" ::: "memory");
        else              asm volatile("cp.async.wait_group 0;" ::: "memory");

        bool valid; (void)jof(e, valid);
        if (valid) {
            uint4 kv = *reinterpret_cast<const uint4*>(kring + (e & 3) * 4096 + tid * 8);
            const __half2* kh = reinterpret_cast<const __half2*>(&kv);
            float d[4];
            #pragma unroll
            for (int qq = 0; qq < 4; qq++) {
                const __half2* q2 = reinterpret_cast<const __half2*>(&qv[qq]);
                __half2 acc = __hmul2(q2[0], kh[0]);
                acc = __hfma2(q2[1], kh[1], acc);
                acc = __hfma2(q2[2], kh[2], acc);
                acc = __hfma2(q2[3], kh[3], acc);
                float2 f = __half22float2(acc);
                d[qq] = f.x + f.y;
            }
            #pragma unroll
            for (int o = 16; o >= 4; o >>= 1) {
                #pragma unroll
                for (int qq = 0; qq < 4; qq++) d[qq] += __shfl_down_sync(0xffffffffu, d[qq], o);
            }
            if (lane < 4) {
                #pragma unroll
                for (int qq = 0; qq < 4; qq++) red2[e][qq][wid * 4 + lane] = d[qq];
            }
        }
        if (e + 4 < 16) {
            bool v_; const int j = jof(e + 4, v_);
            cp16h(kring + ((e + 4) & 3) * 4096 + tid * 8,
                  g_kh + slice + (size_t)j * FDIM + tid * 8);
            asm volatile("cp.async.commit_group;" ::: "memory");
        }
    }

    // start v ring early (overlaps reduction + softmax barriers)
    #pragma unroll
    for (int e = 0; e < 4; e++) {
        bool v_; const int j = jof(e, v_);
        cp16h(vring + (e & 3) * 4096 + tid * 8, g_vh + slice + (size_t)j * FDIM + tid * 8);
        asm volatile("cp.async.commit_group;" ::: "memory");
    }

    __syncthreads();

    if (tid < 64) {
        const int e = tid >> 2, qq = tid & 3;
        float s = 0.f;
        #pragma unroll
        for (int w = 0; w < 64; w++) s += red2[e][qq][w];
        s_sc[e][qq] = s * 0.015625f;   // 1/sqrt(4096)
    }
    __syncthreads();

    // ---- per-query masked softmax (threads 0..3) ----
    if (tid < 4) {
        const int qq = tid;
        const int qy = qy0 + (qq >> 1), qx = qx0 + (qq & 1);
        float sc[16];
        float m = -1e30f;
        #pragma unroll
        for (int e = 0; e < 16; e++) {
            const int ky = qy0 - 1 + (e >> 2), kx = qx0 - 1 + (e & 3);
            const bool valid = (ky >= 0) & (ky < 16) & (kx >= 0) & (kx < 16)
                             & (ky >= qy - 1) & (ky <= qy + 1)
                             & (kx >= qx - 1) & (kx <= qx + 1);
            sc[e] = valid ? s_sc[e][qq] : -1e30f;
            m = fmaxf(m, sc[e]);
        }
        float sum = 0.f;
        float w[16];
        #pragma unroll
        for (int e = 0; e < 16; e++) {
            w[e] = (sc[e] > -1e29f) ? __expf(sc[e] - m) : 0.f;
            sum += w[e];
        }
        const float inv = 1.0f / sum;
        #pragma unroll
        for (int e = 0; e < 16; e++) s_w[qq][e] = w[e] * inv;
    }
    __syncthreads();

    // ---- weighted V: 16 tiles through the ring (fp32 f32x2 accumulate) ----
    u64 fa[4][4];
    #pragma unroll
    for (int qq = 0; qq < 4; qq++)
        #pragma unroll
        for (int u = 0; u < 4; u++) fa[qq][u] = 0ull;

    #pragma unroll
    for (int e = 0; e < 16; e++) {
        if (e < 13)      asm volatile("cp.async.wait_group 3;" ::: "memory");
        else if (e == 13) asm volatile("cp.async.wait_group 2;" ::: "memory");
        else if (e == 14) asm volatile("cp.async.wait_group 1;" ::: "memory");
        else              asm volatile("cp.async.wait_group 0;" ::: "memory");

        bool valid; (void)jof(e, valid);
        if (valid) {
            uint4 vv = *reinterpret_cast<const uint4*>(vring + (e & 3) * 4096 + tid * 8);
            u64 vp[4];
            vp[0] = h2tofx2(vv.x); vp[1] = h2tofx2(vv.y);
            vp[2] = h2tofx2(vv.z); vp[3] = h2tofx2(vv.w);
            #pragma unroll
            for (int qq = 0; qq < 4; qq++) {
                const float a = s_w[qq][e];
                const u64 a2 = pack2(a, a);
                #pragma unroll
                for (int u = 0; u < 4; u++) fa[qq][u] = ffma2(a2, vp[u], fa[qq][u]);
            }
        }
        if (e + 4 < 16) {
            bool v_; const int j = jof(e + 4, v_);
            cp16h(vring + ((e + 4) & 3) * 4096 + tid * 8,
                  g_vh + slice + (size_t)j * FDIM + tid * 8);
            asm volatile("cp.async.commit_group;" ::: "memory");
        }
    }

    __syncthreads();   // all ring reads done before ssa (alias) is written

    // ---- epilogue: stage all 4 queries, then fp16 row stores ----
    const int ch = n & 1, sp = n >> 1, ys = sp >> 1, xs = sp & 1;
    const int sr0 = (tid & 7) * 8;
    const int scc = tid >> 3;
    const int r   = tid >> 3;
    const int cb  = (tid & 7) * 8;
    const int HWp = (ys * 8 + (r >> 3)) * 16 + xs * 8 + (r & 7);

    #pragma unroll
    for (int qq = 0; qq < 4; qq++) {
        #pragma unroll
        for (int u = 0; u < 4; u++) {
            float lo, hi;
            unpack2(fa[qq][u], lo, hi);
            ssa[qq][sr0 + 2 * u    ][scc] = lo;
            ssa[qq][sr0 + 2 * u + 1][scc] = hi;
        }
    }
    __syncthreads();

    #pragma unroll
    for (int qq = 0; qq < 4; qq++) {
        const int i = (qy0 + (qq >> 1)) * 16 + qx0 + (qq & 1);
        __half* rowp = g_sah + (size_t)(b_ * 256 + i) * 32768
                     + (size_t)HWp * 128 + ch * 64 + cb;
        __half2 h0 = __floats2half2_rn(ssa[qq][r][cb + 0], ssa[qq][r][cb + 1]);
        __half2 h1 = __floats2half2_rn(ssa[qq][r][cb + 2], ssa[qq][r][cb + 3]);
        __half2 h2 = __floats2half2_rn(ssa[qq][r][cb + 4], ssa[qq][r][cb + 5]);
        __half2 h3 = __floats2half2_rn(ssa[qq][r][cb + 6], ssa[qq][r][cb + 7]);
        uint4 v;
        v.x = *reinterpret_cast<uint32_t*>(&h0);
        v.y = *reinterpret_cast<uint32_t*>(&h1);
        v.z = *reinterpret_cast<uint32_t*>(&h2);
        v.w = *reinterpret_cast<uint32_t*>(&h3);
        *reinterpret_cast<uint4*>(rowp) = v;
    }
}

// ---------------------------------------------------------------------------
// Kernel C: output projection + bias (R13/R15/R16-proven 2-stage pipeline)
// ---------------------------------------------------------------------------
__global__ __launch_bounds__(256, 2) void out_gemm(const float* __restrict__ b_out,
                                                   float* __restrict__ out) {
    const int t  = blockIdx.x;
    const int pt = blockIdx.y;
    const int tid = threadIdx.x;
    const int lane = tid & 31, wid = tid >> 5;
    const int wm = wid >> 1, wn = wid & 1;

    extern __shared__ __align__(16) __half smem[];
    const __half* xmat = g_sah + (size_t)t * 32768 + pt * 16384;

    auto issue = [&](int buf, int kk) {
        __half* Ab = smem + buf * 18432;
        __half* Bb = Ab + 9216;
        #pragma unroll
        for (int i = 0; i < 4; i++) {
            int id  = tid + i * 256;
            int row = id >> 3, seg = (id & 7) * 8;
            cp16h(Ab + row * PITCH + seg, g_wtoh + row * 128 + kk + seg);
            cp16h(Bb + row * PITCH + seg, xmat + row * 128 + kk + seg);
        }
        asm volatile("cp.async.commit_group;" ::: "memory");
    };

    issue(0, 0);
    issue(1, 64);

    float acc[2][8][4];
    #pragma unroll
    for (int mf = 0; mf < 2; mf++)
        #pragma unroll
        for (int nf = 0; nf < 8; nf++)
            #pragma unroll
            for (int r = 0; r < 4; r++) acc[mf][nf][r] = 0.f;

    const int l7 = lane & 7;
    const int aoff = (l7 + ((lane >> 3) & 1) * 8) * PITCH + ((lane >> 4) & 1) * 8;
    const int boff = (l7 + ((lane >> 4) & 1) * 8) * PITCH + ((lane >> 3) & 1) * 8;

    #pragma unroll
    for (int kt = 0; kt < 2; kt++) {
        if (kt == 0) asm volatile("cp.async.wait_group 1;" ::: "memory");
        else         asm volatile("cp.async.wait_group 0;" ::: "memory");
        __syncthreads();

        const __half* A = smem + kt * 18432;
        const __half* B = A + 9216;

        #pragma unroll
        for (int k0 = 0; k0 < 64; k0 += 16) {
            uint32_t af[2][4], bf[4][4];
            #pragma unroll
            for (int mf = 0; mf < 2; mf++)
                ldsm4(af[mf], A + (wm * 32 + mf * 16) * PITCH + k0 + aoff);
            #pragma unroll
            for (int np = 0; np < 4; np++)
                ldsm4(bf[np], B + (wn * 64 + np * 16) * PITCH + k0 + boff);
            #pragma unroll
            for (int mf = 0; mf < 2; mf++)
                #pragma unroll
                for (int nf = 0; nf < 8; nf++)
                    mma_f16(acc[mf][nf], af[mf],
                            bf[nf >> 1][(nf & 1) * 2], bf[nf >> 1][(nf & 1) * 2 + 1]);
        }
    }

    #pragma unroll
    for (int mf = 0; mf < 2; mf++) {
        #pragma unroll
        for (int half_ = 0; half_ < 2; half_++) {
            const int d = wm * 32 + mf * 16 + (lane >> 2) + half_ * 8;
            const float bias = b_out[d];
            #pragma unroll
            for (int nf = 0; nf < 8; nf++) {
                const int c0 = wn * 64 + nf * 8 + 2 * (lane & 3);
                float2 v = make_float2(acc[mf][nf][half_ * 2] + bias,
                                       acc[mf][nf][half_ * 2 + 1] + bias);
                *reinterpret_cast<float2*>(out + (size_t)t * 32768
                                           + (size_t)d * 256 + pt * 128 + c0) = v;
            }
        }
    }
}

extern "C" void kernel_launch(void* const* d_in, const int* in_sizes, int n_in,
                              void* d_out, int out_size) {
    const float* seq   = (const float*)d_in[0];
    const float* w_qkv = (const float*)d_in[1];
    const float* w_out = (const float*)d_in[2];
    const float* b_out = (const float*)d_in[3];
    float* out = (float*)d_out;

    const int qkvsmem  = 104448;    // X 34816 + W 36864 + staging 32768
    const int outsmem  = 73728;
    const int attnsmem = 83712;     // ssa/ring 66560 + red2 16640 + s_sc 256 + s_w 256
    cudaFuncSetAttribute(qkv_gemm, cudaFuncAttributeMaxDynamicSharedMemorySize, qkvsmem);
    cudaFuncSetAttribute(out_gemm, cudaFuncAttributeMaxDynamicSharedMemorySize, outsmem);
    cudaFuncSetAttribute(attn_kernel, cudaFuncAttributeMaxDynamicSharedMemorySize, attnsmem);

    prep_w<<<192, 256>>>(w_qkv, w_out);

    dim3 gA(NTOK, 2);
    qkv_gemm<<<gA, 256, qkvsmem>>>(seq);

    attn_kernel<<<1024, 512, attnsmem>>>();

    dim3 gC(NTOK, 2);
    out_gemm<<<gC, 256, outsmem>>>(b_out, out);
}